// round 1
// baseline (speedup 1.0000x reference)
#include <cuda_runtime.h>

#define BATCH   8
#define NDATA   8192
#define NPOINT  1024
#define NSAMPLE 32
#define CFEAT   64
#define RADIUSF 0.2f
#define T_LOOSE 0.0401f

#define NP_SIZE  (BATCH*NPOINT*NSAMPLE*(3+CFEAT))   /* 17563648 */
#define IDX_OFF  NP_SIZE
#define IDX_SIZE (BATCH*NPOINT*NSAMPLE)             /* 262144 */
#define GX_OFF   (IDX_OFF + IDX_SIZE)

#define QPW 8   /* queries per warp   */
#define WPB 8   /* warps per block    */
#define CAP 64  /* candidate capacity */

__device__ float g_xs[BATCH*NDATA];
__device__ float g_ys[BATCH*NDATA];
__device__ float g_zs[BATCH*NDATA];

__global__ void k_transpose(const float* __restrict__ xyz)
{
    int t = blockIdx.x * blockDim.x + threadIdx.x;
    if (t < BATCH*NDATA) {
        g_xs[t] = xyz[3*t + 0];
        g_ys[t] = xyz[3*t + 1];
        g_zs[t] = xyz[3*t + 2];
    }
}

__global__ __launch_bounds__(WPB*32, 4)
void k_search(const float* __restrict__ new_xyz, float* __restrict__ out)
{
    __shared__ float s_cd[WPB*QPW][CAP];
    __shared__ int   s_ci[WPB*QPW][CAP];
    __shared__ int   s_cnt[WPB*QPW];
    __shared__ int   s_out[WPB*QPW][NSAMPLE];

    const int b    = blockIdx.y;
    const int w    = threadIdx.x >> 5;
    const int lane = threadIdx.x & 31;
    const int p0   = blockIdx.x * (WPB*QPW) + w*QPW;

    if (lane < QPW) s_cnt[w*QPW + lane] = 0;
    __syncwarp();

    float qx[QPW], qy[QPW], qz[QPW];
#pragma unroll
    for (int q = 0; q < QPW; q++) {
        const float* qp = new_xyz + ((size_t)b*NPOINT + (p0 + q)) * 3;
        qx[q] = qp[0]; qy[q] = qp[1]; qz[q] = qp[2];
    }

    const float* xs = g_xs + b*NDATA;
    const float* ys = g_ys + b*NDATA;
    const float* zs = g_zs + b*NDATA;

    // ---- scan all points; collect loose-radius candidates -----------------
    for (int pt = lane; pt < NDATA; pt += 32) {
        float px = xs[pt], py = ys[pt], pz = zs[pt];
#pragma unroll
        for (int q = 0; q < QPW; q++) {
            float dx = px - qx[q];
            float dy = py - qy[q];
            float dz = pz - qz[q];
            float d2 = fmaf(dx, dx, fmaf(dy, dy, dz*dz));
            if (d2 < T_LOOSE) {
                // exact recompute matching reference arithmetic
                float e = __fadd_rn(__fadd_rn(__fmul_rn(dx,dx), __fmul_rn(dy,dy)),
                                    __fmul_rn(dz,dz));
                float d = __fsqrt_rn(e);
                if (d < RADIUSF) {
                    int ql   = w*QPW + q;
                    int slot = atomicAdd(&s_cnt[ql], 1);
                    if (slot < CAP) { s_cd[ql][slot] = d; s_ci[ql][slot] = pt; }
                }
            }
        }
    }
    __syncwarp();

    // ---- rank candidates, produce idx -------------------------------------
    for (int q = 0; q < QPW; q++) {
        int ql = w*QPW + q;
        int n  = min(s_cnt[ql], CAP);

        if (n == 0) {
            // rare: no point within radius -> global argmin
            float bd = 3.4e38f; int bi = 0;
            for (int pt = lane; pt < NDATA; pt += 32) {
                float dx = xs[pt] - qx[q];
                float dy = ys[pt] - qy[q];
                float dz = zs[pt] - qz[q];
                float e  = __fadd_rn(__fadd_rn(__fmul_rn(dx,dx), __fmul_rn(dy,dy)),
                                     __fmul_rn(dz,dz));
                if (e < bd) { bd = e; bi = pt; }
            }
#pragma unroll
            for (int off = 16; off >= 1; off >>= 1) {
                float od = __shfl_xor_sync(0xffffffffu, bd, off);
                int   oi = __shfl_xor_sync(0xffffffffu, bi, off);
                if (od < bd || (od == bd && oi < bi)) { bd = od; bi = oi; }
            }
            s_out[ql][lane] = bi;
        } else {
            for (int i = lane; i < n; i += 32) {
                float di = s_cd[ql][i]; int ii = s_ci[ql][i];
                int rank = 0;
                for (int j = 0; j < n; j++) {
                    float dj = s_cd[ql][j]; int ij = s_ci[ql][j];
                    rank += (dj < di) || (dj == di && ij < ii);
                }
                if (rank < NSAMPLE) s_out[ql][rank] = ii;
            }
            __syncwarp();
            int nearest = s_out[ql][0];
            if (lane >= n) s_out[ql][lane] = nearest;
        }
        __syncwarp();

        // write idx output (as float values; jnp.concatenate promotes int32->f32)
        int p = p0 + q;
        out[IDX_OFF + ((size_t)(b*NPOINT + p))*NSAMPLE + lane] = (float)s_out[ql][lane];
    }
}

__global__ __launch_bounds__(256)
void k_gather(const float* __restrict__ xyz,
              const float* __restrict__ points,
              float* __restrict__ out)
{
    const int g = threadIdx.x >> 6;   // 4 rows per block
    const int c = threadIdx.x & 63;
    const long r = (long)blockIdx.x * 4 + g;   // 0 .. 262143

    const int b  = (int)(r >> 15);

    const int id = (int)out[IDX_OFF + r];

    const float* prow = points + ((size_t)b*NDATA + id)*CFEAT;
    out[r*67 + 3 + c] = prow[c];

    if (c < 3) {
        float xv = xyz[((size_t)b*NDATA + id)*3 + c];
        out[r*67 + c]       = xv;
        out[GX_OFF + r*3 + c] = xv;
    }
}

extern "C" void kernel_launch(void* const* d_in, const int* in_sizes, int n_in,
                              void* d_out, int out_size)
{
    const float *new_xyz = nullptr, *xyz = nullptr, *points = nullptr;
    for (int i = 0; i < n_in; i++) {
        if      (in_sizes[i] == BATCH*NPOINT*3)     new_xyz = (const float*)d_in[i];
        else if (in_sizes[i] == BATCH*NDATA*3)      xyz     = (const float*)d_in[i];
        else if (in_sizes[i] == BATCH*NDATA*CFEAT)  points  = (const float*)d_in[i];
    }
    float* out = (float*)d_out;

    k_transpose<<<(BATCH*NDATA + 255)/256, 256>>>(xyz);

    dim3 gs(NPOINT/(WPB*QPW), BATCH);
    k_search<<<gs, WPB*32>>>(new_xyz, out);

    k_gather<<<(BATCH*NPOINT*NSAMPLE)/4, 256>>>(xyz, points, out);
}

// round 2
// speedup vs baseline: 1.9151x; 1.9151x over previous
#include <cuda_runtime.h>

#define BATCH   8
#define NDATA   8192
#define NPOINT  1024
#define NSAMPLE 32
#define CFEAT   64
#define RADIUSF 0.2f
#define T_LOOSE 0.0404f

#define NP_SIZE  (BATCH*NPOINT*NSAMPLE*(3+CFEAT))   /* 17563648 */
#define IDX_OFF  NP_SIZE
#define IDX_SIZE (BATCH*NPOINT*NSAMPLE)             /* 262144 */
#define GX_OFF   (IDX_OFF + IDX_SIZE)

#define QB  16   /* queries per block            */
#define WPB 8    /* warps per block (scan chunks)*/
#define CHUNK (NDATA/WPB)                           /* 1024 */
#define CAP 64   /* candidate capacity per query */

__device__ float g_xs[BATCH*NDATA];
__device__ float g_ys[BATCH*NDATA];
__device__ float g_zs[BATCH*NDATA];

__global__ void k_transpose(const float* __restrict__ xyz)
{
    int t = blockIdx.x * blockDim.x + threadIdx.x;
    if (t < BATCH*NDATA) {
        g_xs[t] = xyz[3*t + 0];
        g_ys[t] = xyz[3*t + 1];
        g_zs[t] = xyz[3*t + 2];
    }
}

__global__ __launch_bounds__(WPB*32)
void k_search(const float* __restrict__ new_xyz, float* __restrict__ out)
{
    __shared__ float s_cd[QB][CAP];
    __shared__ int   s_ci[QB][CAP];
    __shared__ int   s_cnt[QB];
    __shared__ int   s_out[QB][NSAMPLE];

    const int b    = blockIdx.y;
    const int w    = threadIdx.x >> 5;
    const int lane = threadIdx.x & 31;
    const int p0   = blockIdx.x * QB;

    if (threadIdx.x < QB) s_cnt[threadIdx.x] = 0;
    __syncthreads();

    // query coords in registers (compile-time indexed only)
    float qx[QB], qy[QB], qz[QB], qt[QB];
#pragma unroll
    for (int q = 0; q < QB; q++) {
        const float* qp = new_xyz + ((size_t)b*NPOINT + (p0 + q)) * 3;
        qx[q] = qp[0]; qy[q] = qp[1]; qz[q] = qp[2];
        // loose threshold folded with |q|^2:  pp - 2t < T_LOOSE - |q|^2
        qt[q] = T_LOOSE - fmaf(qx[q],qx[q], fmaf(qy[q],qy[q], qz[q]*qz[q]));
    }

    const float* xs = g_xs + b*NDATA;
    const float* ys = g_ys + b*NDATA;
    const float* zs = g_zs + b*NDATA;

    // ---- each warp scans its 1024-point chunk for all QB queries ----------
    const int ptEnd = (w+1)*CHUNK;
    for (int pt = w*CHUNK + lane; pt < ptEnd; pt += 32) {
        float px = xs[pt], py = ys[pt], pz = zs[pt];
        float pp = fmaf(px,px, fmaf(py,py, pz*pz));
#pragma unroll
        for (int q = 0; q < QB; q++) {
            float t  = fmaf(pz,qz[q], fmaf(py,qy[q], px*qx[q]));
            float lhs = fmaf(-2.0f, t, pp);          // pp - 2 p.q
            if (lhs < qt[q]) {
                // exact recompute matching reference arithmetic
                float dx = px - qx[q];
                float dy = py - qy[q];
                float dz = pz - qz[q];
                float e = __fadd_rn(__fadd_rn(__fmul_rn(dx,dx), __fmul_rn(dy,dy)),
                                    __fmul_rn(dz,dz));
                float d = __fsqrt_rn(e);
                if (d < RADIUSF) {
                    int slot = atomicAdd(&s_cnt[q], 1);
                    if (slot < CAP) { s_cd[q][slot] = d; s_ci[q][slot] = pt; }
                }
            }
        }
    }
    __syncthreads();

    // ---- rank candidates: warp w handles queries 2w, 2w+1 -----------------
    for (int qq = 0; qq < QB/WPB; qq++) {
        const int q = w*(QB/WPB) + qq;
        const int n = min(s_cnt[q], CAP);
        const int p = p0 + q;

        if (n == 0) {
            // rare: no point in radius -> global argmin (reload query coords)
            const float* qp = new_xyz + ((size_t)b*NPOINT + p) * 3;
            float cx = qp[0], cy = qp[1], cz = qp[2];
            float bd = 3.4e38f; int bi = 0;
            for (int pt = lane; pt < NDATA; pt += 32) {
                float dx = xs[pt] - cx;
                float dy = ys[pt] - cy;
                float dz = zs[pt] - cz;
                float e  = __fadd_rn(__fadd_rn(__fmul_rn(dx,dx), __fmul_rn(dy,dy)),
                                     __fmul_rn(dz,dz));
                if (e < bd) { bd = e; bi = pt; }
            }
#pragma unroll
            for (int off = 16; off >= 1; off >>= 1) {
                float od = __shfl_xor_sync(0xffffffffu, bd, off);
                int   oi = __shfl_xor_sync(0xffffffffu, bi, off);
                if (od < bd || (od == bd && oi < bi)) { bd = od; bi = oi; }
            }
            s_out[q][lane] = bi;
        } else {
            for (int i = lane; i < n; i += 32) {
                float di = s_cd[q][i]; int ii = s_ci[q][i];
                int rank = 0;
                for (int j = 0; j < n; j++) {
                    float dj = s_cd[q][j]; int ij = s_ci[q][j];
                    rank += (dj < di) || (dj == di && ij < ii);
                }
                if (rank < NSAMPLE) s_out[q][rank] = ii;
            }
            __syncwarp();
            int nearest = s_out[q][0];
            if (lane >= n) s_out[q][lane] = nearest;
        }
        __syncwarp();

        out[IDX_OFF + ((size_t)(b*NPOINT + p))*NSAMPLE + lane] = (float)s_out[q][lane];
    }
}

__global__ __launch_bounds__(256)
void k_gather(const float* __restrict__ xyz,
              const float* __restrict__ points,
              float* __restrict__ out)
{
    const int g = threadIdx.x >> 6;   // 4 rows per block
    const int c = threadIdx.x & 63;
    const long r = (long)blockIdx.x * 4 + g;   // 0 .. 262143

    const int b  = (int)(r >> 15);

    const int id = (int)out[IDX_OFF + r];

    const float* prow = points + ((size_t)b*NDATA + id)*CFEAT;
    out[r*67 + 3 + c] = prow[c];

    if (c < 3) {
        float xv = xyz[((size_t)b*NDATA + id)*3 + c];
        out[r*67 + c]         = xv;
        out[GX_OFF + r*3 + c] = xv;
    }
}

extern "C" void kernel_launch(void* const* d_in, const int* in_sizes, int n_in,
                              void* d_out, int out_size)
{
    const float *new_xyz = nullptr, *xyz = nullptr, *points = nullptr;
    for (int i = 0; i < n_in; i++) {
        if      (in_sizes[i] == BATCH*NPOINT*3)     new_xyz = (const float*)d_in[i];
        else if (in_sizes[i] == BATCH*NDATA*3)      xyz     = (const float*)d_in[i];
        else if (in_sizes[i] == BATCH*NDATA*CFEAT)  points  = (const float*)d_in[i];
    }
    float* out = (float*)d_out;

    k_transpose<<<(BATCH*NDATA + 255)/256, 256>>>(xyz);

    dim3 gs(NPOINT/QB, BATCH);
    k_search<<<gs, WPB*32>>>(new_xyz, out);

    k_gather<<<(BATCH*NPOINT*NSAMPLE)/4, 256>>>(xyz, points, out);
}

// round 3
// speedup vs baseline: 2.4855x; 1.2979x over previous
#include <cuda_runtime.h>

#define BATCH   8
#define NDATA   8192
#define NPOINT  1024
#define NSAMPLE 32
#define CFEAT   64
#define RADIUSF 0.2f
#define T_LOOSE 0.0404f

#define NP_SIZE  (BATCH*NPOINT*NSAMPLE*(3+CFEAT))   /* 17563648 */
#define IDX_OFF  NP_SIZE
#define IDX_SIZE (BATCH*NPOINT*NSAMPLE)             /* 262144 */
#define GX_OFF   (IDX_OFF + IDX_SIZE)

#define QB  16   /* queries per block             */
#define WPB 8    /* warps per block (scan chunks) */
#define CHUNK (NDATA/WPB)                           /* 1024 */
#define CAP 64   /* candidate capacity per query  */

__device__ float4 g_pts[BATCH*NDATA];   /* (x, y, z, |p|^2) */

__global__ void k_transpose(const float* __restrict__ xyz)
{
    int t = blockIdx.x * blockDim.x + threadIdx.x;
    if (t < BATCH*NDATA) {
        float x = xyz[3*t + 0];
        float y = xyz[3*t + 1];
        float z = xyz[3*t + 2];
        float pp = fmaf(x, x, fmaf(y, y, z*z));
        g_pts[t] = make_float4(x, y, z, pp);
    }
}

__global__ __launch_bounds__(WPB*32)
void k_search(const float* __restrict__ new_xyz, float* __restrict__ out)
{
    __shared__ float s_cd[QB][CAP];
    __shared__ int   s_ci[QB][CAP];
    __shared__ int   s_cnt[QB];
    __shared__ int   s_out[QB][NSAMPLE];
    __shared__ float s_qx[QB], s_qy[QB], s_qz[QB];

    const int b    = blockIdx.y;
    const int w    = threadIdx.x >> 5;
    const int lane = threadIdx.x & 31;
    const int p0   = blockIdx.x * QB;

    if (threadIdx.x < QB) {
        s_cnt[threadIdx.x] = 0;
        const float* qp = new_xyz + ((size_t)b*NPOINT + p0 + threadIdx.x) * 3;
        s_qx[threadIdx.x] = qp[0];
        s_qy[threadIdx.x] = qp[1];
        s_qz[threadIdx.x] = qp[2];
    }
    __syncthreads();

    // per-thread query constants (compile-time indexed -> registers)
    float nqx[QB], nqy[QB], nqz[QB], qt[QB];
#pragma unroll
    for (int q = 0; q < QB; q++) {
        float cx = s_qx[q], cy = s_qy[q], cz = s_qz[q];
        nqx[q] = -2.0f*cx; nqy[q] = -2.0f*cy; nqz[q] = -2.0f*cz;
        // loose test: |p|^2 - 2 p.q < T_LOOSE - |q|^2
        qt[q] = T_LOOSE - fmaf(cx,cx, fmaf(cy,cy, cz*cz));
    }

    const float4* pts = g_pts + b*NDATA;

    // ---- hot loop: branchless mask, rare slow path ------------------------
    const int ptEnd = (w+1)*CHUNK;
    for (int pt = w*CHUNK + lane; pt < ptEnd; pt += 32) {
        float4 P = pts[pt];
        unsigned m = 0;
#pragma unroll
        for (int q = 0; q < QB; q++) {
            float l = fmaf(P.x, nqx[q], fmaf(P.y, nqy[q], fmaf(P.z, nqz[q], P.w)));
            if (l < qt[q]) m |= (1u << q);
        }
        while (m) {
            int q = __ffs(m) - 1;
            m &= m - 1;
            // exact recompute matching reference arithmetic
            float dx = P.x - s_qx[q];
            float dy = P.y - s_qy[q];
            float dz = P.z - s_qz[q];
            float e = __fadd_rn(__fadd_rn(__fmul_rn(dx,dx), __fmul_rn(dy,dy)),
                                __fmul_rn(dz,dz));
            float d = __fsqrt_rn(e);
            if (d < RADIUSF) {
                int slot = atomicAdd(&s_cnt[q], 1);
                if (slot < CAP) { s_cd[q][slot] = d; s_ci[q][slot] = pt; }
            }
        }
    }
    __syncthreads();

    // ---- rank candidates: warp w handles queries 2w, 2w+1 -----------------
    for (int qq = 0; qq < QB/WPB; qq++) {
        const int q = w*(QB/WPB) + qq;
        const int n = min(s_cnt[q], CAP);
        const int p = p0 + q;

        if (n == 0) {
            // rare: nothing within radius -> global argmin
            float cx = s_qx[q], cy = s_qy[q], cz = s_qz[q];
            float bd = 3.4e38f; int bi = 0;
            for (int pt = lane; pt < NDATA; pt += 32) {
                float4 P = pts[pt];
                float dx = P.x - cx;
                float dy = P.y - cy;
                float dz = P.z - cz;
                float e  = __fadd_rn(__fadd_rn(__fmul_rn(dx,dx), __fmul_rn(dy,dy)),
                                     __fmul_rn(dz,dz));
                if (e < bd) { bd = e; bi = pt; }
            }
#pragma unroll
            for (int off = 16; off >= 1; off >>= 1) {
                float od = __shfl_xor_sync(0xffffffffu, bd, off);
                int   oi = __shfl_xor_sync(0xffffffffu, bi, off);
                if (od < bd || (od == bd && oi < bi)) { bd = od; bi = oi; }
            }
            s_out[q][lane] = bi;
        } else {
            for (int i = lane; i < n; i += 32) {
                float di = s_cd[q][i]; int ii = s_ci[q][i];
                int rank = 0;
                for (int j = 0; j < n; j++) {
                    float dj = s_cd[q][j]; int ij = s_ci[q][j];
                    rank += (dj < di) || (dj == di && ij < ii);
                }
                if (rank < NSAMPLE) s_out[q][rank] = ii;
            }
            __syncwarp();
            int nearest = s_out[q][0];
            if (lane >= n) s_out[q][lane] = nearest;
        }
        __syncwarp();

        out[IDX_OFF + ((size_t)(b*NPOINT + p))*NSAMPLE + lane] = (float)s_out[q][lane];
    }
}

__global__ __launch_bounds__(256)
void k_gather(const float* __restrict__ xyz,
              const float* __restrict__ points,
              float* __restrict__ out)
{
    const int g = threadIdx.x >> 6;   // 4 rows per block
    const int c = threadIdx.x & 63;
    const long r = (long)blockIdx.x * 4 + g;   // 0 .. 262143

    const int b  = (int)(r >> 15);

    const int id = (int)out[IDX_OFF + r];

    const float* prow = points + ((size_t)b*NDATA + id)*CFEAT;
    out[r*67 + 3 + c] = prow[c];

    if (c < 3) {
        float xv = xyz[((size_t)b*NDATA + id)*3 + c];
        out[r*67 + c]         = xv;
        out[GX_OFF + r*3 + c] = xv;
    }
}

extern "C" void kernel_launch(void* const* d_in, const int* in_sizes, int n_in,
                              void* d_out, int out_size)
{
    const float *new_xyz = nullptr, *xyz = nullptr, *points = nullptr;
    for (int i = 0; i < n_in; i++) {
        if      (in_sizes[i] == BATCH*NPOINT*3)     new_xyz = (const float*)d_in[i];
        else if (in_sizes[i] == BATCH*NDATA*3)      xyz     = (const float*)d_in[i];
        else if (in_sizes[i] == BATCH*NDATA*CFEAT)  points  = (const float*)d_in[i];
    }
    float* out = (float*)d_out;

    k_transpose<<<(BATCH*NDATA + 255)/256, 256>>>(xyz);

    dim3 gs(NPOINT/QB, BATCH);
    k_search<<<gs, WPB*32>>>(new_xyz, out);

    k_gather<<<(BATCH*NPOINT*NSAMPLE)/4, 256>>>(xyz, points, out);
}